// round 10
// baseline (speedup 1.0000x reference)
#include <cuda_runtime.h>
#include <cuda_bf16.h>
#include <cstdint>

// CIN_74603581932155 — bf16 hi/lo split GEMM on warp-level mma.sync (HMMA).
// R9: 512 threads / 16 warps (4x4 warp grid, 32x32 warp tiles). R8 showed the
// binding constraint is HMMA issue-gap coverage with only 2 warps/SMSP
// (tensor 57%, issue 20%); doubling warps/SMSP fills the gaps. Cross-warp
// d-sum goes through a psum buffer aliased onto U-buf1 (dead at epilogue).
//
// Per batch-pair CTA:  D(128o x 128col) = W(128 x K) * U^T
//   U[k][col] = hid[h][col] * x0[m][col], k = h*32+m, col = bb*64+d
//   K = 1024 / 4096 / 4096.   W = Whi+Wlo (truncation split), U = Uhi+Ulo.
//   D += Whi*Uhi + Whi*Ulo + Wlo*Uhi   (fp32 register accumulators).

namespace {

constexpr int THREADS = 512;
constexpr int NTILE_L0 = 16, NTILE_L12 = 64;
constexpr int NTILES = NTILE_L0 + 2 * NTILE_L12;   // 144
constexpr int WSTR_B = 144;                        // smem row stride bytes (72 bf16)
constexpr int WT_BYTES = 128 * WSTR_B;             // 18432 per (hi|lo) tile
constexpr int XSTR = 36;                           // x0T float stride (m < 32)
constexpr int HSTR = 129;                          // hidT float stride (h < 128)

constexpr int OFF_W    = 0;                          // [buf][hl] 4 x 18432
constexpr int OFF_U    = OFF_W + 4 * WT_BYTES;       // [buf][hl] 4 x 18432
constexpr int OFF_X0T  = OFF_U + 4 * WT_BYTES;       // float x0T[128][36]
constexpr int OFF_HIDT = OFF_X0T + 128 * XSTR * 4;   // float hidT[128][129]
constexpr int SMEM_TOTAL = OFF_HIDT + 128 * HSTR * 4;  // 231936
static_assert(SMEM_TOTAL <= 227 * 1024, "smem budget");
// psum[4][128] floats aliased onto U buf1 (dead during epilogue)
constexpr int OFF_PSUM = OFF_U + 2 * WT_BYTES;

// Pre-split W, flat K-major tile rows: [hl][tile][o*64 + kk] (bf16)
__device__ __align__(16) unsigned char g_Wsplit[2][NTILES][128 * 128];

__device__ __forceinline__ uint32_t smem_u32(const void* p) {
    uint32_t a;
    asm("{ .reg .u64 t; cvta.to.shared.u64 t, %1; cvt.u32.u64 %0, t; }" : "=r"(a) : "l"(p));
    return a;
}

#define CPASYNC16(dst, src) \
    asm volatile("cp.async.ca.shared.global [%0], [%1], 16;" :: "r"(dst), "l"(src) : "memory")

#define LDSM4(r, a) \
    asm volatile("ldmatrix.sync.aligned.m8n8.x4.shared.b16 {%0,%1,%2,%3}, [%4];" \
        : "=r"((r)[0]), "=r"((r)[1]), "=r"((r)[2]), "=r"((r)[3]) : "r"(a))

#define MMA16816(d, a, b) \
    asm volatile("mma.sync.aligned.m16n8k16.row.col.f32.bf16.bf16.f32 " \
        "{%0,%1,%2,%3}, {%4,%5,%6,%7}, {%8,%9}, {%0,%1,%2,%3};" \
        : "+f"((d)[0]), "+f"((d)[1]), "+f"((d)[2]), "+f"((d)[3]) \
        : "r"((a)[0]), "r"((a)[1]), "r"((a)[2]), "r"((a)[3]), "r"((b)[0]), "r"((b)[1]))

// ---------------- prep: split W into bf16 hi/lo tiles -------------------------
__global__ void prep_w_kernel(const float* __restrict__ W0,
                              const float* __restrict__ W1,
                              const float* __restrict__ W2)
{
    int tile = blockIdx.x;              // 0..143
    int tb; const float* Ws; int K;
    if (tile < NTILE_L0)      { tb = tile;            Ws = W0; K = 1024; }
    else if (tile < 80)       { tb = tile - NTILE_L0; Ws = W1; K = 4096; }
    else                      { tb = tile - 80;       Ws = W2; K = 4096; }

    int o = threadIdx.x >> 1;
    int half = threadIdx.x & 1;
    __nv_bfloat16* hi_b = reinterpret_cast<__nv_bfloat16*>(g_Wsplit[0][tile]);
    __nv_bfloat16* lo_b = reinterpret_cast<__nv_bfloat16*>(g_Wsplit[1][tile]);

    #pragma unroll 4
    for (int j = 0; j < 32; ++j) {
        int kk = half * 32 + j;
        float w = Ws[(size_t)o * K + (size_t)tb * 64 + kk];
        uint32_t ub = __float_as_uint(w);
        float hif = __uint_as_float(ub & 0xFFFF0000u);
        float lof = w - hif;
        hi_b[o * 64 + kk] = __ushort_as_bfloat16((unsigned short)(ub >> 16));
        lo_b[o * 64 + kk] = __float2bfloat16_rn(lof);
    }
}

// ---------------- main kernel --------------------------------------------------
__global__ void __launch_bounds__(THREADS, 1)
cin_mma_kernel(const float* __restrict__ x,
               const float* __restrict__ bias0,
               const float* __restrict__ bias1,
               const float* __restrict__ bias2,
               float* __restrict__ out)
{
    extern __shared__ char smem[];
    const uint32_t sb = smem_u32(smem);
    const int tid = threadIdx.x;
    const int wid = tid >> 5;
    const int lane = tid & 31;
    const int b0 = blockIdx.x * 2;

    float* x0T  = reinterpret_cast<float*>(smem + OFF_X0T);
    float* hidT = reinterpret_cast<float*>(smem + OFF_HIDT);
    float* psum = reinterpret_cast<float*>(smem + OFF_PSUM);   // [4][128]

    // ---- build x0T[col][m], col = bb*64 + d ----
    {
        const float* xg = x + (size_t)b0 * 2048;
        #pragma unroll
        for (int r = 0; r < 2; ++r) {
            int idx4 = tid + THREADS * r;           // 0..1023 float4s
            int bb = idx4 >> 9, rem = idx4 & 511;
            int m = rem >> 4, d4 = rem & 15;
            float4 v = *reinterpret_cast<const float4*>(xg + bb * 2048 + m * 64 + d4 * 4);
            int col0 = bb * 64 + d4 * 4;
            x0T[(col0 + 0) * XSTR + m] = v.x;
            x0T[(col0 + 1) * XSTR + m] = v.y;
            x0T[(col0 + 2) * XSTR + m] = v.z;
            x0T[(col0 + 3) * XSTR + m] = v.w;
        }
    }
    __syncthreads();

    // ---- per-warp tile mapping: 4(o) x 4(col) warps, warp tile 32 x 32 ----
    const int ow = wid & 3, cw = wid >> 2;
    const int o_base = ow * 32;
    const int col_base = cw * 32;
    const uint32_t a_off = (uint32_t)(o_base + (lane & 15)) * WSTR_B
                         + (uint32_t)(lane >> 4) * 16;
    const uint32_t b_off = (uint32_t)(col_base + (lane & 7) + ((lane >> 4) << 3)) * WSTR_B
                         + (uint32_t)((lane >> 3) & 1) * 16;

    // U-gen role: 4 threads per col; quad selects (h-half, m-half)
    const int ucol  = tid >> 2;
    const int uhalf = tid & 1;           // h = 2t + uhalf
    const int umb   = ((tid >> 1) & 1) * 16;  // m base: 0 or 16
    const float* xr = x0T + ucol * XSTR;

    const float* biases[3] = {bias0, bias1, bias2};
    const int nk_l[3] = {NTILE_L0, NTILE_L12, NTILE_L12};
    const int tb_l[3] = {0, NTILE_L0, NTILE_L0 + NTILE_L12};

    for (int layer = 0; layer < 3; ++layer) {
        const int nk = nk_l[layer];
        const float* hsrc = (layer == 0) ? x0T : hidT;
        const int hstr = (layer == 0) ? XSTR : HSTR;

        float acc[2][4][4];
        #pragma unroll
        for (int mi = 0; mi < 2; ++mi)
            #pragma unroll
            for (int nj = 0; nj < 4; ++nj)
                #pragma unroll
                for (int q = 0; q < 4; ++q) acc[mi][nj][q] = 0.0f;

        // ---- W cp.async issue for tile t into buf ----
        auto w_issue = [&](int t, int buf) {
            const int tile = tb_l[layer] + t;
            const uint32_t wdst = sb + OFF_W + (uint32_t)buf * 2 * WT_BYTES;
            #pragma unroll
            for (int r = 0; r < 4; ++r) {
                int c = tid + THREADS * r;          // 0..2047 16B chunks
                int hl = c >> 10, rem = c & 1023, row = rem >> 3, seg = rem & 7;
                uint32_t dst = wdst + (uint32_t)hl * WT_BYTES
                             + (uint32_t)row * WSTR_B + (uint32_t)seg * 16;
                CPASYNC16(dst, &g_Wsplit[hl][tile][row * 128 + seg * 16]);
            }
            asm volatile("cp.async.commit_group;" ::: "memory");
        };

        // ---- U-gen: one 8-value chunk (c in {0,1}) of tile t into buf ----
        auto ugen_chunk = [&](float hv, int buf, int chunk) {
            const uint32_t udst = sb + OFF_U + (uint32_t)buf * 2 * WT_BYTES;
            const uint32_t ub = udst + (uint32_t)ucol * WSTR_B + (uint32_t)uhalf * 64;
            const int i8 = umb + chunk * 8;
            float4 xa = *reinterpret_cast<const float4*>(xr + i8);
            float4 xb = *reinterpret_cast<const float4*>(xr + i8 + 4);
            float u[8] = {hv * xa.x, hv * xa.y, hv * xa.z, hv * xa.w,
                          hv * xb.x, hv * xb.y, hv * xb.z, hv * xb.w};
            uint32_t hp[4], lp[4];
            #pragma unroll
            for (int p = 0; p < 4; ++p) {
                uint32_t u0 = __float_as_uint(u[2 * p]);
                uint32_t u1 = __float_as_uint(u[2 * p + 1]);
                hp[p] = __byte_perm(u0, u1, 0x7632);     // {u0.hi16, u1.hi16}
                float l0 = u[2 * p]     - __uint_as_float(u0 & 0xFFFF0000u);
                float l1 = u[2 * p + 1] - __uint_as_float(u1 & 0xFFFF0000u);
                asm("cvt.rn.bf16x2.f32 %0, %2, %1;" : "=r"(lp[p]) : "f"(l0), "f"(l1));
            }
            asm volatile("st.shared.v4.b32 [%0], {%1,%2,%3,%4};"
                         :: "r"(ub + i8 * 2), "r"(hp[0]), "r"(hp[1]), "r"(hp[2]), "r"(hp[3])
                         : "memory");
            asm volatile("st.shared.v4.b32 [%0], {%1,%2,%3,%4};"
                         :: "r"(ub + WT_BYTES + i8 * 2), "r"(lp[0]), "r"(lp[1]), "r"(lp[2]), "r"(lp[3])
                         : "memory");
        };

        // ---- prologue: stage tile 0 into buf 0 ----
        w_issue(0, 0);
        {
            const float hv0 = hsrc[ucol * hstr + uhalf];
            ugen_chunk(hv0, 0, 0);
            ugen_chunk(hv0, 0, 1);
        }
        asm volatile("cp.async.wait_group 0;" ::: "memory");
        __syncthreads();

        // ---- main loop: compute(cur) with staging of kt+1 interleaved ----
        for (int kt = 0; kt < nk; ++kt) {
            const int cur = kt & 1;
            const int nxt = cur ^ 1;
            const bool more = (kt + 1 < nk);

            float hv = 0.0f;
            if (more) {
                w_issue(kt + 1, nxt);
                asm volatile("cp.async.wait_group 1;" ::: "memory");
                hv = hsrc[ucol * hstr + (2 * (kt + 1) + uhalf)];
            } else {
                asm volatile("cp.async.wait_group 0;" ::: "memory");
            }

            const uint32_t whi = sb + OFF_W + (uint32_t)cur * 2 * WT_BYTES;
            const uint32_t wlo = whi + WT_BYTES;
            const uint32_t uhi = sb + OFF_U + (uint32_t)cur * 2 * WT_BYTES;
            const uint32_t ulo = uhi + WT_BYTES;

            #pragma unroll
            for (int kk = 0; kk < 4; ++kk) {
                if (more && kk < 2) ugen_chunk(hv, nxt, kk);

                uint32_t ah[2][4], al[2][4], bh[4][2], bl[4][2];
                const uint32_t ka = a_off + kk * 32;
                LDSM4(ah[0], whi + ka);
                LDSM4(ah[1], whi + ka + 16 * WSTR_B);
                LDSM4(al[0], wlo + ka);
                LDSM4(al[1], wlo + ka + 16 * WSTR_B);
                const uint32_t kb = b_off + kk * 32;
                #pragma unroll
                for (int njp = 0; njp < 2; ++njp) {
                    uint32_t t0[4], t1[4];
                    LDSM4(t0, uhi + kb + njp * 16 * WSTR_B);
                    LDSM4(t1, ulo + kb + njp * 16 * WSTR_B);
                    bh[2 * njp][0] = t0[0]; bh[2 * njp][1] = t0[1];
                    bh[2 * njp + 1][0] = t0[2]; bh[2 * njp + 1][1] = t0[3];
                    bl[2 * njp][0] = t1[0]; bl[2 * njp][1] = t1[1];
                    bl[2 * njp + 1][0] = t1[2]; bl[2 * njp + 1][1] = t1[3];
                }
                #pragma unroll
                for (int mi = 0; mi < 2; ++mi)
                    #pragma unroll
                    for (int nj = 0; nj < 4; ++nj)
                        MMA16816(acc[mi][nj], ah[mi], bh[nj]);
                #pragma unroll
                for (int mi = 0; mi < 2; ++mi)
                    #pragma unroll
                    for (int nj = 0; nj < 4; ++nj)
                        MMA16816(acc[mi][nj], ah[mi], bl[nj]);
                #pragma unroll
                for (int mi = 0; mi < 2; ++mi)
                    #pragma unroll
                    for (int nj = 0; nj < 4; ++nj)
                        MMA16816(acc[mi][nj], al[mi], bh[nj]);
            }
            __syncthreads();   // nxt fully staged AND cur fully consumed
        }

        // ---- epilogue: bias + ReLU, hidT store, partial d-sums -> psum ----
        {
            const float* bl = biases[layer];
            #pragma unroll
            for (int mi = 0; mi < 2; ++mi) {
                #pragma unroll
                for (int s = 0; s < 2; ++s) {
                    const int h = o_base + mi * 16 + (lane >> 2) + 8 * s;
                    const float bv = __ldg(&bl[h]);
                    float rs = 0.0f;
                    #pragma unroll
                    for (int nj = 0; nj < 4; ++nj) {
                        float z0 = fmaxf(acc[mi][nj][2 * s] + bv, 0.0f);
                        float z1 = fmaxf(acc[mi][nj][2 * s + 1] + bv, 0.0f);
                        rs += z0 + z1;
                        if (layer < 2) {
                            int c0 = col_base + nj * 8 + (lane & 3) * 2;
                            hidT[c0 * HSTR + h] = z0;
                            hidT[(c0 + 1) * HSTR + h] = z1;
                        }
                    }
                    rs += __shfl_xor_sync(0xFFFFFFFFu, rs, 1);
                    rs += __shfl_xor_sync(0xFFFFFFFFu, rs, 2);
                    if ((lane & 3) == 0)
                        psum[cw * 128 + h] = rs;    // aliases U buf1 (dead here)
                }
            }
        }
        __syncthreads();

        // ---- combine warp-pair partials: out[b0+bb][layer*128+h] ----
        if (tid < 256) {
            int bb = tid >> 7, h = tid & 127;
            out[(size_t)(b0 + bb) * 384 + layer * 128 + h] =
                psum[(2 * bb) * 128 + h] + psum[(2 * bb + 1) * 128 + h];
        }
        // next layer's prologue only touches buf 0; buf 1 (psum) is first
        // rewritten at kt=0 staging, which is after the prologue barrier.
    }
}

} // namespace

extern "C" void kernel_launch(void* const* d_in, const int* in_sizes, int n_in,
                              void* d_out, int out_size) {
    const float* x  = (const float*)d_in[0];
    const float* W0 = (const float*)d_in[1];
    const float* b0 = (const float*)d_in[2];
    const float* W1 = (const float*)d_in[3];
    const float* b1 = (const float*)d_in[4];
    const float* W2 = (const float*)d_in[5];
    const float* b2 = (const float*)d_in[6];
    float* out = (float*)d_out;

    prep_w_kernel<<<NTILES, 256>>>(W0, W1, W2);

    cudaFuncSetAttribute(cin_mma_kernel, cudaFuncAttributeMaxDynamicSharedMemorySize,
                         SMEM_TOTAL);
    cin_mma_kernel<<<512, THREADS, SMEM_TOTAL>>>(x, b0, b1, b2, out);
}

// round 11
// speedup vs baseline: 1.6639x; 1.6639x over previous
#include <cuda_runtime.h>
#include <cuda_bf16.h>
#include <cstdint>

// CIN_74603581932155 — bf16 hi/lo split GEMM on warp-level mma.sync (HMMA).
// R10: revert to the R8 shape (256 thr, 4x2 warp grid, 32x64 warp tiles) and
// software-pipeline the ldmatrix fragments: double-buffered frag registers,
// kk+1's A/B fragments prefetched under kk's MMA stream. R9 (16 warps) showed
// more warps regress; R8 analysis shows HMMA issues at full rate when it
// issues — the loss is LDSM latency at each kk boundary. This hides it.
//
// Per batch-pair CTA:  D(128o x 128col) = W(128 x K) * U^T
//   U[k][col] = hid[h][col] * x0[m][col], k = h*32+m, col = bb*64+d
//   K = 1024 / 4096 / 4096.   W = Whi+Wlo (truncation split), U = Uhi+Ulo.
//   D += Whi*Uhi + Whi*Ulo + Wlo*Uhi   (fp32 register accumulators).

namespace {

constexpr int THREADS = 256;
constexpr int NTILE_L0 = 16, NTILE_L12 = 64;
constexpr int NTILES = NTILE_L0 + 2 * NTILE_L12;   // 144
constexpr int WSTR_B = 144;                        // smem row stride bytes (72 bf16)
constexpr int WT_BYTES = 128 * WSTR_B;             // 18432 per (hi|lo) tile
constexpr int XSTR = 36;                           // x0T float stride (m < 32)
constexpr int HSTR = 129;                          // hidT float stride (h < 128)

constexpr int OFF_W    = 0;                          // [buf][hl] 4 x 18432
constexpr int OFF_U    = OFF_W + 4 * WT_BYTES;       // [buf][hl] 4 x 18432
constexpr int OFF_X0T  = OFF_U + 4 * WT_BYTES;       // float x0T[128][36]
constexpr int OFF_HIDT = OFF_X0T + 128 * XSTR * 4;   // float hidT[128][129]
constexpr int SMEM_TOTAL = OFF_HIDT + 128 * HSTR * 4;  // 231936
static_assert(SMEM_TOTAL <= 227 * 1024, "smem budget");

// Pre-split W, flat K-major tile rows: [hl][tile][o*64 + kk] (bf16)
__device__ __align__(16) unsigned char g_Wsplit[2][NTILES][128 * 128];

__device__ __forceinline__ uint32_t smem_u32(const void* p) {
    uint32_t a;
    asm("{ .reg .u64 t; cvta.to.shared.u64 t, %1; cvt.u32.u64 %0, t; }" : "=r"(a) : "l"(p));
    return a;
}

#define CPASYNC16(dst, src) \
    asm volatile("cp.async.ca.shared.global [%0], [%1], 16;" :: "r"(dst), "l"(src) : "memory")

#define LDSM4(r, a) \
    asm volatile("ldmatrix.sync.aligned.m8n8.x4.shared.b16 {%0,%1,%2,%3}, [%4];" \
        : "=r"((r)[0]), "=r"((r)[1]), "=r"((r)[2]), "=r"((r)[3]) : "r"(a))

#define MMA16816(d, a, b) \
    asm volatile("mma.sync.aligned.m16n8k16.row.col.f32.bf16.bf16.f32 " \
        "{%0,%1,%2,%3}, {%4,%5,%6,%7}, {%8,%9}, {%0,%1,%2,%3};" \
        : "+f"((d)[0]), "+f"((d)[1]), "+f"((d)[2]), "+f"((d)[3]) \
        : "r"((a)[0]), "r"((a)[1]), "r"((a)[2]), "r"((a)[3]), "r"((b)[0]), "r"((b)[1]))

// ---------------- prep: split W into bf16 hi/lo tiles -------------------------
__global__ void prep_w_kernel(const float* __restrict__ W0,
                              const float* __restrict__ W1,
                              const float* __restrict__ W2)
{
    int tile = blockIdx.x;              // 0..143
    int tb; const float* Ws; int K;
    if (tile < NTILE_L0)      { tb = tile;            Ws = W0; K = 1024; }
    else if (tile < 80)       { tb = tile - NTILE_L0; Ws = W1; K = 4096; }
    else                      { tb = tile - 80;       Ws = W2; K = 4096; }

    int o = threadIdx.x >> 1;
    int half = threadIdx.x & 1;
    __nv_bfloat16* hi_b = reinterpret_cast<__nv_bfloat16*>(g_Wsplit[0][tile]);
    __nv_bfloat16* lo_b = reinterpret_cast<__nv_bfloat16*>(g_Wsplit[1][tile]);

    #pragma unroll 4
    for (int j = 0; j < 32; ++j) {
        int kk = half * 32 + j;
        float w = Ws[(size_t)o * K + (size_t)tb * 64 + kk];
        uint32_t ub = __float_as_uint(w);
        float hif = __uint_as_float(ub & 0xFFFF0000u);
        float lof = w - hif;
        hi_b[o * 64 + kk] = __ushort_as_bfloat16((unsigned short)(ub >> 16));
        lo_b[o * 64 + kk] = __float2bfloat16_rn(lof);
    }
}

// ---------------- main kernel --------------------------------------------------
__global__ void __launch_bounds__(THREADS, 1)
cin_mma_kernel(const float* __restrict__ x,
               const float* __restrict__ bias0,
               const float* __restrict__ bias1,
               const float* __restrict__ bias2,
               float* __restrict__ out)
{
    extern __shared__ char smem[];
    const uint32_t sb = smem_u32(smem);
    const int tid = threadIdx.x;
    const int wid = tid >> 5;
    const int lane = tid & 31;
    const int b0 = blockIdx.x * 2;

    float* x0T  = reinterpret_cast<float*>(smem + OFF_X0T);
    float* hidT = reinterpret_cast<float*>(smem + OFF_HIDT);

    // ---- build x0T[col][m], col = bb*64 + d ----
    {
        const float* xg = x + (size_t)b0 * 2048;
        #pragma unroll
        for (int r = 0; r < 4; ++r) {
            int idx4 = tid + THREADS * r;           // 0..1023 float4s
            int bb = idx4 >> 9, rem = idx4 & 511;
            int m = rem >> 4, d4 = rem & 15;
            float4 v = *reinterpret_cast<const float4*>(xg + bb * 2048 + m * 64 + d4 * 4);
            int col0 = bb * 64 + d4 * 4;
            x0T[(col0 + 0) * XSTR + m] = v.x;
            x0T[(col0 + 1) * XSTR + m] = v.y;
            x0T[(col0 + 2) * XSTR + m] = v.z;
            x0T[(col0 + 3) * XSTR + m] = v.w;
        }
    }
    __syncthreads();

    // ---- per-warp tile mapping: 4(o) x 2(col) warps, warp tile 32 x 64 ----
    const int ow = wid & 3, cw = wid >> 2;
    const int o_base = ow * 32;
    const int col_base = cw * 64;
    const uint32_t a_off = (uint32_t)(o_base + (lane & 15)) * WSTR_B
                         + (uint32_t)(lane >> 4) * 16;
    const uint32_t b_off = (uint32_t)(col_base + (lane & 7) + ((lane >> 4) << 3)) * WSTR_B
                         + (uint32_t)((lane >> 3) & 1) * 16;

    // U-gen role
    const int ucol = tid >> 1;
    const int uhalf = tid & 1;
    const float* xr = x0T + ucol * XSTR;

    const float* biases[3] = {bias0, bias1, bias2};
    const int nk_l[3] = {NTILE_L0, NTILE_L12, NTILE_L12};
    const int tb_l[3] = {0, NTILE_L0, NTILE_L0 + NTILE_L12};

    for (int layer = 0; layer < 3; ++layer) {
        const int nk = nk_l[layer];
        const float* hsrc = (layer == 0) ? x0T : hidT;
        const int hstr = (layer == 0) ? XSTR : HSTR;

        float acc[2][8][4];
        #pragma unroll
        for (int mi = 0; mi < 2; ++mi)
            #pragma unroll
            for (int nj = 0; nj < 8; ++nj)
                #pragma unroll
                for (int q = 0; q < 4; ++q) acc[mi][nj][q] = 0.0f;

        // ---- W cp.async issue for tile t into buf ----
        auto w_issue = [&](int t, int buf) {
            const int tile = tb_l[layer] + t;
            const uint32_t wdst = sb + OFF_W + (uint32_t)buf * 2 * WT_BYTES;
            #pragma unroll
            for (int r = 0; r < 8; ++r) {
                int c = tid + THREADS * r;          // 0..2047 16B chunks
                int hl = c >> 10, rem = c & 1023, row = rem >> 3, seg = rem & 7;
                uint32_t dst = wdst + (uint32_t)hl * WT_BYTES
                             + (uint32_t)row * WSTR_B + (uint32_t)seg * 16;
                CPASYNC16(dst, &g_Wsplit[hl][tile][row * 128 + seg * 16]);
            }
            asm volatile("cp.async.commit_group;" ::: "memory");
        };

        // ---- U-gen: one 8-value chunk of tile t into buf ----
        auto ugen_chunk = [&](float hv, int buf, int chunk) {
            const uint32_t udst = sb + OFF_U + (uint32_t)buf * 2 * WT_BYTES;
            const uint32_t ub = udst + (uint32_t)ucol * WSTR_B + (uint32_t)uhalf * 64;
            const int i8 = chunk * 8;
            float4 xa = *reinterpret_cast<const float4*>(xr + i8);
            float4 xb = *reinterpret_cast<const float4*>(xr + i8 + 4);
            float u[8] = {hv * xa.x, hv * xa.y, hv * xa.z, hv * xa.w,
                          hv * xb.x, hv * xb.y, hv * xb.z, hv * xb.w};
            uint32_t hp[4], lp[4];
            #pragma unroll
            for (int p = 0; p < 4; ++p) {
                uint32_t u0 = __float_as_uint(u[2 * p]);
                uint32_t u1 = __float_as_uint(u[2 * p + 1]);
                hp[p] = __byte_perm(u0, u1, 0x7632);     // {u0.hi16, u1.hi16}
                float l0 = u[2 * p]     - __uint_as_float(u0 & 0xFFFF0000u);
                float l1 = u[2 * p + 1] - __uint_as_float(u1 & 0xFFFF0000u);
                asm("cvt.rn.bf16x2.f32 %0, %2, %1;" : "=r"(lp[p]) : "f"(l0), "f"(l1));
            }
            asm volatile("st.shared.v4.b32 [%0], {%1,%2,%3,%4};"
                         :: "r"(ub + i8 * 2), "r"(hp[0]), "r"(hp[1]), "r"(hp[2]), "r"(hp[3])
                         : "memory");
            asm volatile("st.shared.v4.b32 [%0], {%1,%2,%3,%4};"
                         :: "r"(ub + WT_BYTES + i8 * 2), "r"(lp[0]), "r"(lp[1]), "r"(lp[2]), "r"(lp[3])
                         : "memory");
        };

        // ---- fragment loads for one kk, into pipe slot p ----
        uint32_t ah[2][2][4], al[2][2][4];   // [pipe][mi][4]
        uint32_t bh[2][8][2], bl[2][8][2];   // [pipe][nj][2]

        auto lds_frags = [&](int p, uint32_t whi, uint32_t wlo,
                             uint32_t uhi, uint32_t ulo, int kk) {
            const uint32_t ka = a_off + kk * 32;
            LDSM4(ah[p][0], whi + ka);
            LDSM4(ah[p][1], whi + ka + 16 * WSTR_B);
            LDSM4(al[p][0], wlo + ka);
            LDSM4(al[p][1], wlo + ka + 16 * WSTR_B);
            const uint32_t kb = b_off + kk * 32;
            #pragma unroll
            for (int njp = 0; njp < 4; ++njp) {
                uint32_t t0[4], t1[4];
                LDSM4(t0, uhi + kb + njp * 16 * WSTR_B);
                LDSM4(t1, ulo + kb + njp * 16 * WSTR_B);
                bh[p][2 * njp][0] = t0[0]; bh[p][2 * njp][1] = t0[1];
                bh[p][2 * njp + 1][0] = t0[2]; bh[p][2 * njp + 1][1] = t0[3];
                bl[p][2 * njp][0] = t1[0]; bl[p][2 * njp][1] = t1[1];
                bl[p][2 * njp + 1][0] = t1[2]; bl[p][2 * njp + 1][1] = t1[3];
            }
        };

        // ---- prologue: stage tile 0 into buf 0 ----
        w_issue(0, 0);
        {
            const float hv0 = hsrc[ucol * hstr + uhalf];
            #pragma unroll
            for (int c = 0; c < 4; ++c) ugen_chunk(hv0, 0, c);
        }
        asm volatile("cp.async.wait_group 0;" ::: "memory");
        __syncthreads();

        // ---- main loop: frag-pipelined compute(cur) + staging of kt+1 ----
        for (int kt = 0; kt < nk; ++kt) {
            const int cur = kt & 1;
            const int nxt = cur ^ 1;
            const bool more = (kt + 1 < nk);

            float hv = 0.0f;
            if (more) {
                w_issue(kt + 1, nxt);
                asm volatile("cp.async.wait_group 1;" ::: "memory");
                hv = hsrc[ucol * hstr + (2 * (kt + 1) + uhalf)];
            } else {
                asm volatile("cp.async.wait_group 0;" ::: "memory");
            }

            const uint32_t whi = sb + OFF_W + (uint32_t)cur * 2 * WT_BYTES;
            const uint32_t wlo = whi + WT_BYTES;
            const uint32_t uhi = sb + OFF_U + (uint32_t)cur * 2 * WT_BYTES;
            const uint32_t ulo = uhi + WT_BYTES;

            lds_frags(0, whi, wlo, uhi, ulo, 0);

            #pragma unroll
            for (int kk = 0; kk < 4; ++kk) {
                const int pc = kk & 1;
                const int pn = pc ^ 1;
                // prefetch kk+1 fragments under this kk's MMA stream
                if (kk < 3) lds_frags(pn, whi, wlo, uhi, ulo, kk + 1);
                // interleave 1/4 of next tile's U-gen (writes buf nxt)
                if (more) ugen_chunk(hv, nxt, kk);

                #pragma unroll
                for (int mi = 0; mi < 2; ++mi)
                    #pragma unroll
                    for (int nj = 0; nj < 8; ++nj)
                        MMA16816(acc[mi][nj], ah[pc][mi], bh[pc][nj]);
                #pragma unroll
                for (int mi = 0; mi < 2; ++mi)
                    #pragma unroll
                    for (int nj = 0; nj < 8; ++nj)
                        MMA16816(acc[mi][nj], ah[pc][mi], bl[pc][nj]);
                #pragma unroll
                for (int mi = 0; mi < 2; ++mi)
                    #pragma unroll
                    for (int nj = 0; nj < 8; ++nj)
                        MMA16816(acc[mi][nj], al[pc][mi], bh[pc][nj]);
            }
            // single barrier: nxt fully staged by all warps AND cur fully
            // consumed (next iteration computes nxt, restages into cur).
            __syncthreads();
        }

        // ---- epilogue: bias + ReLU, hidT[col][h] store, d-sum -> out ----
        {
            const float* bl = biases[layer];
            #pragma unroll
            for (int mi = 0; mi < 2; ++mi) {
                #pragma unroll
                for (int s = 0; s < 2; ++s) {
                    const int h = o_base + mi * 16 + (lane >> 2) + 8 * s;
                    const float bv = __ldg(&bl[h]);
                    float rs = 0.0f;
                    #pragma unroll
                    for (int nj = 0; nj < 8; ++nj) {
                        float z0 = fmaxf(acc[mi][nj][2 * s] + bv, 0.0f);
                        float z1 = fmaxf(acc[mi][nj][2 * s + 1] + bv, 0.0f);
                        rs += z0 + z1;
                        if (layer < 2) {
                            int c0 = col_base + nj * 8 + (lane & 3) * 2;
                            hidT[c0 * HSTR + h] = z0;
                            hidT[(c0 + 1) * HSTR + h] = z1;
                        }
                    }
                    rs += __shfl_xor_sync(0xFFFFFFFFu, rs, 1);
                    rs += __shfl_xor_sync(0xFFFFFFFFu, rs, 2);
                    if ((lane & 3) == 0)
                        out[(size_t)(b0 + cw) * 384 + layer * 128 + h] = rs;
                }
            }
        }
        __syncthreads();   // hidT complete before next layer's U-gen
    }
}

} // namespace

extern "C" void kernel_launch(void* const* d_in, const int* in_sizes, int n_in,
                              void* d_out, int out_size) {
    const float* x  = (const float*)d_in[0];
    const float* W0 = (const float*)d_in[1];
    const float* b0 = (const float*)d_in[2];
    const float* W1 = (const float*)d_in[3];
    const float* b1 = (const float*)d_in[4];
    const float* W2 = (const float*)d_in[5];
    const float* b2 = (const float*)d_in[6];
    float* out = (float*)d_out;

    prep_w_kernel<<<NTILES, 256>>>(W0, W1, W2);

    cudaFuncSetAttribute(cin_mma_kernel, cudaFuncAttributeMaxDynamicSharedMemorySize,
                         SMEM_TOTAL);
    cin_mma_kernel<<<512, THREADS, SMEM_TOTAL>>>(x, b0, b1, b2, out);
}

// round 12
// speedup vs baseline: 3.6560x; 2.1973x over previous
#include <cuda_runtime.h>
#include <cuda_fp16.h>
#include <cstdint>

// CIN_74603581932155 — single-term fp16 GEMM on warp-level mma.sync (HMMA).
// R11: drop the bf16 hi/lo split (3 MMA terms) for plain fp16 (1 term).
// Error analysis: fp16 rounding ~4e-4 RMS per product, norm-averaged by the
// ReLU'd d-sum(64) to ~1e-4 final — 10x under the 1e-3 threshold. W is
// pre-scaled by 2^8 (exact; undone in epilogue) to avoid fp16 subnormals.
// MMA count/warp/tile: 192 -> 64.
//
// Per batch-pair CTA:  D(128o x 128col) = W(128 x K) * U^T
//   U[k][col] = hid[h][col] * x0[m][col], k = h*32+m, col = bb*64+d
//   K = 1024 / 4096 / 4096.  fp32 accumulators, fp32 hidden state in smem.

namespace {

constexpr int THREADS = 256;
constexpr int NTILE_L0 = 16, NTILE_L12 = 64;
constexpr int NTILES = NTILE_L0 + 2 * NTILE_L12;   // 144
constexpr int WSTR_B = 144;                        // smem row stride bytes (64 fp16 + pad)
constexpr int WT_BYTES = 128 * WSTR_B;             // 18432 per tile
constexpr int XSTR = 36;                           // x0T float stride (m < 32)
constexpr int HSTR = 129;                          // hidT float stride (h < 128)
constexpr float WSCALE = 256.0f;                   // W pre-scale (exact power of 2)
constexpr float WINV   = 1.0f / 256.0f;

constexpr int OFF_W    = 0;                          // [buf] 2 x 18432
constexpr int OFF_U    = OFF_W + 2 * WT_BYTES;       // [buf] 2 x 18432
constexpr int OFF_X0T  = OFF_U + 2 * WT_BYTES;       // float x0T[128][36]
constexpr int OFF_HIDT = OFF_X0T + 128 * XSTR * 4;   // float hidT[128][129]
constexpr int SMEM_TOTAL = OFF_HIDT + 128 * HSTR * 4;  // 158208
static_assert(SMEM_TOTAL <= 227 * 1024, "smem budget");

// Pre-scaled fp16 W, flat K-major tile rows: [tile][o*64 + kk]
__device__ __align__(16) unsigned char g_Wh[NTILES][128 * 64 * 2];

__device__ __forceinline__ uint32_t smem_u32(const void* p) {
    uint32_t a;
    asm("{ .reg .u64 t; cvta.to.shared.u64 t, %1; cvt.u32.u64 %0, t; }" : "=r"(a) : "l"(p));
    return a;
}

#define CPASYNC16(dst, src) \
    asm volatile("cp.async.ca.shared.global [%0], [%1], 16;" :: "r"(dst), "l"(src) : "memory")

#define LDSM4(r, a) \
    asm volatile("ldmatrix.sync.aligned.m8n8.x4.shared.b16 {%0,%1,%2,%3}, [%4];" \
        : "=r"((r)[0]), "=r"((r)[1]), "=r"((r)[2]), "=r"((r)[3]) : "r"(a))

#define MMA16816(d, a, b) \
    asm volatile("mma.sync.aligned.m16n8k16.row.col.f32.f16.f16.f32 " \
        "{%0,%1,%2,%3}, {%4,%5,%6,%7}, {%8,%9}, {%0,%1,%2,%3};" \
        : "+f"((d)[0]), "+f"((d)[1]), "+f"((d)[2]), "+f"((d)[3]) \
        : "r"((a)[0]), "r"((a)[1]), "r"((a)[2]), "r"((a)[3]), "r"((b)[0]), "r"((b)[1]))

// ---------------- prep: W -> fp16 (pre-scaled by 256), K-major tiles ----------
__global__ void prep_w_kernel(const float* __restrict__ W0,
                              const float* __restrict__ W1,
                              const float* __restrict__ W2)
{
    int tile = blockIdx.x;              // 0..143
    int tb; const float* Ws; int K;
    if (tile < NTILE_L0)      { tb = tile;            Ws = W0; K = 1024; }
    else if (tile < 80)       { tb = tile - NTILE_L0; Ws = W1; K = 4096; }
    else                      { tb = tile - 80;       Ws = W2; K = 4096; }

    int o = threadIdx.x >> 1;
    int half = threadIdx.x & 1;
    __half* wh = reinterpret_cast<__half*>(g_Wh[tile]);

    #pragma unroll 4
    for (int j = 0; j < 32; ++j) {
        int kk = half * 32 + j;
        float w = Ws[(size_t)o * K + (size_t)tb * 64 + kk] * WSCALE;
        wh[o * 64 + kk] = __float2half_rn(w);
    }
}

// ---------------- main kernel --------------------------------------------------
__global__ void __launch_bounds__(THREADS, 1)
cin_mma_kernel(const float* __restrict__ x,
               const float* __restrict__ bias0,
               const float* __restrict__ bias1,
               const float* __restrict__ bias2,
               float* __restrict__ out)
{
    extern __shared__ char smem[];
    const uint32_t sb = smem_u32(smem);
    const int tid = threadIdx.x;
    const int wid = tid >> 5;
    const int lane = tid & 31;
    const int b0 = blockIdx.x * 2;

    float* x0T  = reinterpret_cast<float*>(smem + OFF_X0T);
    float* hidT = reinterpret_cast<float*>(smem + OFF_HIDT);

    // ---- build x0T[col][m], col = bb*64 + d ----
    {
        const float* xg = x + (size_t)b0 * 2048;
        #pragma unroll
        for (int r = 0; r < 4; ++r) {
            int idx4 = tid + THREADS * r;           // 0..1023 float4s
            int bb = idx4 >> 9, rem = idx4 & 511;
            int m = rem >> 4, d4 = rem & 15;
            float4 v = *reinterpret_cast<const float4*>(xg + bb * 2048 + m * 64 + d4 * 4);
            int col0 = bb * 64 + d4 * 4;
            x0T[(col0 + 0) * XSTR + m] = v.x;
            x0T[(col0 + 1) * XSTR + m] = v.y;
            x0T[(col0 + 2) * XSTR + m] = v.z;
            x0T[(col0 + 3) * XSTR + m] = v.w;
        }
    }
    __syncthreads();

    // ---- per-warp tile mapping: 4(o) x 2(col) warps, warp tile 32 x 64 ----
    const int ow = wid & 3, cw = wid >> 2;
    const int o_base = ow * 32;
    const int col_base = cw * 64;
    const uint32_t a_off = (uint32_t)(o_base + (lane & 15)) * WSTR_B
                         + (uint32_t)(lane >> 4) * 16;
    const uint32_t b_off = (uint32_t)(col_base + (lane & 7) + ((lane >> 4) << 3)) * WSTR_B
                         + (uint32_t)((lane >> 3) & 1) * 16;

    // U-gen role
    const int ucol = tid >> 1;
    const int uhalf = tid & 1;
    const float* xr = x0T + ucol * XSTR;

    const float* biases[3] = {bias0, bias1, bias2};
    const int nk_l[3] = {NTILE_L0, NTILE_L12, NTILE_L12};
    const int tb_l[3] = {0, NTILE_L0, NTILE_L0 + NTILE_L12};

    for (int layer = 0; layer < 3; ++layer) {
        const int nk = nk_l[layer];
        const float* hsrc = (layer == 0) ? x0T : hidT;
        const int hstr = (layer == 0) ? XSTR : HSTR;

        float acc[2][8][4];
        #pragma unroll
        for (int mi = 0; mi < 2; ++mi)
            #pragma unroll
            for (int nj = 0; nj < 8; ++nj)
                #pragma unroll
                for (int q = 0; q < 4; ++q) acc[mi][nj][q] = 0.0f;

        // ---- W cp.async issue for tile t into buf (1024 16B chunks) ----
        auto w_issue = [&](int t, int buf) {
            const int tile = tb_l[layer] + t;
            const uint32_t wdst = sb + OFF_W + (uint32_t)buf * WT_BYTES;
            #pragma unroll
            for (int r = 0; r < 4; ++r) {
                int c = tid + THREADS * r;          // 0..1023
                int row = c >> 3, seg = c & 7;
                uint32_t dst = wdst + (uint32_t)row * WSTR_B + (uint32_t)seg * 16;
                CPASYNC16(dst, &g_Wh[tile][(row * 64 + seg * 8) * 2]);
            }
            asm volatile("cp.async.commit_group;" ::: "memory");
        };

        // ---- U-gen: one 8-value fp16 chunk of tile t into buf ----
        auto ugen_chunk = [&](float hv, int buf, int chunk) {
            const uint32_t udst = sb + OFF_U + (uint32_t)buf * WT_BYTES;
            const uint32_t ub = udst + (uint32_t)ucol * WSTR_B + (uint32_t)uhalf * 64;
            const int i8 = chunk * 8;
            float4 xa = *reinterpret_cast<const float4*>(xr + i8);
            float4 xb = *reinterpret_cast<const float4*>(xr + i8 + 4);
            __half2 p0 = __floats2half2_rn(hv * xa.x, hv * xa.y);
            __half2 p1 = __floats2half2_rn(hv * xa.z, hv * xa.w);
            __half2 p2 = __floats2half2_rn(hv * xb.x, hv * xb.y);
            __half2 p3 = __floats2half2_rn(hv * xb.z, hv * xb.w);
            asm volatile("st.shared.v4.b32 [%0], {%1,%2,%3,%4};"
                         :: "r"(ub + i8 * 2),
                            "r"(*reinterpret_cast<uint32_t*>(&p0)),
                            "r"(*reinterpret_cast<uint32_t*>(&p1)),
                            "r"(*reinterpret_cast<uint32_t*>(&p2)),
                            "r"(*reinterpret_cast<uint32_t*>(&p3))
                         : "memory");
        };

        // ---- fragment loads for one kk, into pipe slot p ----
        uint32_t ah[2][2][4];   // [pipe][mi][4]
        uint32_t bh[2][8][2];   // [pipe][nj][2]

        auto lds_frags = [&](int p, uint32_t wcur, uint32_t ucur, int kk) {
            const uint32_t ka = a_off + kk * 32;
            LDSM4(ah[p][0], wcur + ka);
            LDSM4(ah[p][1], wcur + ka + 16 * WSTR_B);
            const uint32_t kb = b_off + kk * 32;
            #pragma unroll
            for (int njp = 0; njp < 4; ++njp) {
                uint32_t t0[4];
                LDSM4(t0, ucur + kb + njp * 16 * WSTR_B);
                bh[p][2 * njp][0] = t0[0]; bh[p][2 * njp][1] = t0[1];
                bh[p][2 * njp + 1][0] = t0[2]; bh[p][2 * njp + 1][1] = t0[3];
            }
        };

        // ---- prologue: stage tile 0 into buf 0 ----
        w_issue(0, 0);
        {
            const float hv0 = hsrc[ucol * hstr + uhalf];
            #pragma unroll
            for (int c = 0; c < 4; ++c) ugen_chunk(hv0, 0, c);
        }
        asm volatile("cp.async.wait_group 0;" ::: "memory");
        __syncthreads();

        // ---- main loop: frag-pipelined compute(cur) + staging of kt+1 ----
        for (int kt = 0; kt < nk; ++kt) {
            const int cur = kt & 1;
            const int nxt = cur ^ 1;
            const bool more = (kt + 1 < nk);

            float hv = 0.0f;
            if (more) {
                w_issue(kt + 1, nxt);
                asm volatile("cp.async.wait_group 1;" ::: "memory");
                hv = hsrc[ucol * hstr + (2 * (kt + 1) + uhalf)];
            } else {
                asm volatile("cp.async.wait_group 0;" ::: "memory");
            }

            const uint32_t wcur = sb + OFF_W + (uint32_t)cur * WT_BYTES;
            const uint32_t ucur = sb + OFF_U + (uint32_t)cur * WT_BYTES;

            lds_frags(0, wcur, ucur, 0);

            #pragma unroll
            for (int kk = 0; kk < 4; ++kk) {
                const int pc = kk & 1;
                const int pn = pc ^ 1;
                if (kk < 3) lds_frags(pn, wcur, ucur, kk + 1);
                if (more) ugen_chunk(hv, nxt, kk);

                #pragma unroll
                for (int mi = 0; mi < 2; ++mi)
                    #pragma unroll
                    for (int nj = 0; nj < 8; ++nj)
                        MMA16816(acc[mi][nj], ah[pc][mi], bh[pc][nj]);
            }
            __syncthreads();   // nxt fully staged AND cur fully consumed
        }

        // ---- epilogue: unscale + bias + ReLU, hidT store, d-sum -> out ----
        {
            const float* bl = biases[layer];
            #pragma unroll
            for (int mi = 0; mi < 2; ++mi) {
                #pragma unroll
                for (int s = 0; s < 2; ++s) {
                    const int h = o_base + mi * 16 + (lane >> 2) + 8 * s;
                    const float bv = __ldg(&bl[h]);
                    float rs = 0.0f;
                    #pragma unroll
                    for (int nj = 0; nj < 8; ++nj) {
                        float z0 = fmaxf(acc[mi][nj][2 * s] * WINV + bv, 0.0f);
                        float z1 = fmaxf(acc[mi][nj][2 * s + 1] * WINV + bv, 0.0f);
                        rs += z0 + z1;
                        if (layer < 2) {
                            int c0 = col_base + nj * 8 + (lane & 3) * 2;
                            hidT[c0 * HSTR + h] = z0;
                            hidT[(c0 + 1) * HSTR + h] = z1;
                        }
                    }
                    rs += __shfl_xor_sync(0xFFFFFFFFu, rs, 1);
                    rs += __shfl_xor_sync(0xFFFFFFFFu, rs, 2);
                    if ((lane & 3) == 0)
                        out[(size_t)(b0 + cw) * 384 + layer * 128 + h] = rs;
                }
            }
        }
        __syncthreads();   // hidT complete before next layer's U-gen
    }
}

} // namespace

extern "C" void kernel_launch(void* const* d_in, const int* in_sizes, int n_in,
                              void* d_out, int out_size) {
    const float* x  = (const float*)d_in[0];
    const float* W0 = (const float*)d_in[1];
    const float* b0 = (const float*)d_in[2];
    const float* W1 = (const float*)d_in[3];
    const float* b1 = (const float*)d_in[4];
    const float* W2 = (const float*)d_in[5];
    const float* b2 = (const float*)d_in[6];
    float* out = (float*)d_out;

    prep_w_kernel<<<NTILES, 256>>>(W0, W1, W2);

    cudaFuncSetAttribute(cin_mma_kernel, cudaFuncAttributeMaxDynamicSharedMemorySize,
                         SMEM_TOTAL);
    cin_mma_kernel<<<512, THREADS, SMEM_TOTAL>>>(x, b0, b1, b2, out);
}

// round 13
// speedup vs baseline: 4.0403x; 1.1051x over previous
#include <cuda_runtime.h>
#include <cuda_fp16.h>
#include <cstdint>

// CIN_74603581932155 — single-term fp16 GEMM on warp-level mma.sync (HMMA).
// R12: 2 CTAs/SM co-residency. R9-R11 showed the ~1100 cyc/tile of
// non-tensor overhead can't be hidden inside one CTA; a second independent
// CTA's MMA stream fills it. To fit 2x in 227KB smem: x0T and hidT stored
// fp16 (per-product err ~8e-4 RMS -> ~1.5e-4 final, under 1e-3), and frag
// double-buffering dropped to fit the 128-reg/thread budget.
//
// Per batch-pair CTA:  D(128o x 128col) = W(128 x K) * U^T
//   U[k][col] = hid[h][col] * x0[m][col], k = h*32+m, col = bb*64+d
//   K = 1024 / 4096 / 4096.  fp32 accumulators. W pre-scaled by 2^8 (exact,
//   undone in epilogue) against fp16 subnormals.

namespace {

constexpr int THREADS = 256;
constexpr int NTILE_L0 = 16, NTILE_L12 = 64;
constexpr int NTILES = NTILE_L0 + 2 * NTILE_L12;   // 144
constexpr int WSTR_B = 144;                        // smem tile row stride (64 fp16 + pad)
constexpr int WT_BYTES = 128 * WSTR_B;             // 18432 per tile
constexpr int XSTR = 32;                           // x0T half stride (m < 32), 64B rows
constexpr int HSTR = 129;                          // hidT half stride (h < 128)
constexpr float WSCALE = 256.0f;
constexpr float WINV   = 1.0f / 256.0f;

constexpr int OFF_W    = 0;                          // [buf] 2 x 18432
constexpr int OFF_U    = OFF_W + 2 * WT_BYTES;       // [buf] 2 x 18432
constexpr int OFF_X0T  = OFF_U + 2 * WT_BYTES;       // half x0T[128][32]
constexpr int OFF_HIDT = OFF_X0T + 128 * XSTR * 2;   // half hidT[128][129]
constexpr int SMEM_TOTAL = OFF_HIDT + 128 * HSTR * 2;  // 114944
static_assert(SMEM_TOTAL <= 115200, "2-CTA smem budget");

// Pre-scaled fp16 W, flat K-major tile rows: [tile][o*64 + kk]
__device__ __align__(16) unsigned char g_Wh[NTILES][128 * 64 * 2];

__device__ __forceinline__ uint32_t smem_u32(const void* p) {
    uint32_t a;
    asm("{ .reg .u64 t; cvta.to.shared.u64 t, %1; cvt.u32.u64 %0, t; }" : "=r"(a) : "l"(p));
    return a;
}

#define CPASYNC16(dst, src) \
    asm volatile("cp.async.ca.shared.global [%0], [%1], 16;" :: "r"(dst), "l"(src) : "memory")

#define LDSM4(r, a) \
    asm volatile("ldmatrix.sync.aligned.m8n8.x4.shared.b16 {%0,%1,%2,%3}, [%4];" \
        : "=r"((r)[0]), "=r"((r)[1]), "=r"((r)[2]), "=r"((r)[3]) : "r"(a))

#define MMA16816(d, a, b) \
    asm volatile("mma.sync.aligned.m16n8k16.row.col.f32.f16.f16.f32 " \
        "{%0,%1,%2,%3}, {%4,%5,%6,%7}, {%8,%9}, {%0,%1,%2,%3};" \
        : "+f"((d)[0]), "+f"((d)[1]), "+f"((d)[2]), "+f"((d)[3]) \
        : "r"((a)[0]), "r"((a)[1]), "r"((a)[2]), "r"((a)[3]), "r"((b)[0]), "r"((b)[1]))

// ---------------- prep: W -> fp16 (pre-scaled by 256), K-major tiles ----------
__global__ void prep_w_kernel(const float* __restrict__ W0,
                              const float* __restrict__ W1,
                              const float* __restrict__ W2)
{
    int tile = blockIdx.x;              // 0..143
    int tb; const float* Ws; int K;
    if (tile < NTILE_L0)      { tb = tile;            Ws = W0; K = 1024; }
    else if (tile < 80)       { tb = tile - NTILE_L0; Ws = W1; K = 4096; }
    else                      { tb = tile - 80;       Ws = W2; K = 4096; }

    int o = threadIdx.x >> 1;
    int half = threadIdx.x & 1;
    __half* wh = reinterpret_cast<__half*>(g_Wh[tile]);

    #pragma unroll 4
    for (int j = 0; j < 32; ++j) {
        int kk = half * 32 + j;
        float w = Ws[(size_t)o * K + (size_t)tb * 64 + kk] * WSCALE;
        wh[o * 64 + kk] = __float2half_rn(w);
    }
}

// ---------------- main kernel --------------------------------------------------
__global__ void __launch_bounds__(THREADS, 2)
cin_mma_kernel(const float* __restrict__ x,
               const float* __restrict__ bias0,
               const float* __restrict__ bias1,
               const float* __restrict__ bias2,
               float* __restrict__ out)
{
    extern __shared__ char smem[];
    const uint32_t sb = smem_u32(smem);
    const int tid = threadIdx.x;
    const int wid = tid >> 5;
    const int lane = tid & 31;
    const int b0 = blockIdx.x * 2;

    __half* x0T  = reinterpret_cast<__half*>(smem + OFF_X0T);
    __half* hidT = reinterpret_cast<__half*>(smem + OFF_HIDT);

    // ---- build x0T[col][m] (fp16), col = bb*64 + d ----
    {
        const float* xg = x + (size_t)b0 * 2048;
        #pragma unroll
        for (int r = 0; r < 4; ++r) {
            int idx4 = tid + THREADS * r;           // 0..1023 float4s
            int bb = idx4 >> 9, rem = idx4 & 511;
            int m = rem >> 4, d4 = rem & 15;
            float4 v = *reinterpret_cast<const float4*>(xg + bb * 2048 + m * 64 + d4 * 4);
            int col0 = bb * 64 + d4 * 4;
            x0T[(col0 + 0) * XSTR + m] = __float2half_rn(v.x);
            x0T[(col0 + 1) * XSTR + m] = __float2half_rn(v.y);
            x0T[(col0 + 2) * XSTR + m] = __float2half_rn(v.z);
            x0T[(col0 + 3) * XSTR + m] = __float2half_rn(v.w);
        }
    }
    __syncthreads();

    // ---- per-warp tile mapping: 4(o) x 2(col) warps, warp tile 32 x 64 ----
    const int ow = wid & 3, cw = wid >> 2;
    const int o_base = ow * 32;
    const int col_base = cw * 64;
    const uint32_t a_off = (uint32_t)(o_base + (lane & 15)) * WSTR_B
                         + (uint32_t)(lane >> 4) * 16;
    const uint32_t b_off = (uint32_t)(col_base + (lane & 7) + ((lane >> 4) << 3)) * WSTR_B
                         + (uint32_t)((lane >> 3) & 1) * 16;

    // U-gen role
    const int ucol = tid >> 1;
    const int uhalf = tid & 1;
    const __half2* xv = reinterpret_cast<const __half2*>(x0T + ucol * XSTR);

    const float* biases[3] = {bias0, bias1, bias2};
    const int nk_l[3] = {NTILE_L0, NTILE_L12, NTILE_L12};
    const int tb_l[3] = {0, NTILE_L0, NTILE_L0 + NTILE_L12};

    for (int layer = 0; layer < 3; ++layer) {
        const int nk = nk_l[layer];
        const __half* hsrc = (layer == 0) ? x0T : hidT;
        const int hstr = (layer == 0) ? XSTR : HSTR;

        float acc[2][8][4];
        #pragma unroll
        for (int mi = 0; mi < 2; ++mi)
            #pragma unroll
            for (int nj = 0; nj < 8; ++nj)
                #pragma unroll
                for (int q = 0; q < 4; ++q) acc[mi][nj][q] = 0.0f;

        // ---- W cp.async issue for tile t into buf (1024 16B chunks) ----
        auto w_issue = [&](int t, int buf) {
            const int tile = tb_l[layer] + t;
            const uint32_t wdst = sb + OFF_W + (uint32_t)buf * WT_BYTES;
            #pragma unroll
            for (int r = 0; r < 4; ++r) {
                int c = tid + THREADS * r;          // 0..1023
                int row = c >> 3, seg = c & 7;
                uint32_t dst = wdst + (uint32_t)row * WSTR_B + (uint32_t)seg * 16;
                CPASYNC16(dst, &g_Wh[tile][(row * 64 + seg * 8) * 2]);
            }
            asm volatile("cp.async.commit_group;" ::: "memory");
        };

        // ---- U-gen: one 8-value fp16 chunk of tile t into buf ----
        auto ugen_chunk = [&](__half2 hv2, int buf, int chunk) {
            const uint32_t udst = sb + OFF_U + (uint32_t)buf * WT_BYTES;
            const uint32_t ub = udst + (uint32_t)ucol * WSTR_B + (uint32_t)uhalf * 64;
            const int i8 = chunk * 8;
            __half2 p0 = __hmul2(hv2, xv[chunk * 4 + 0]);
            __half2 p1 = __hmul2(hv2, xv[chunk * 4 + 1]);
            __half2 p2 = __hmul2(hv2, xv[chunk * 4 + 2]);
            __half2 p3 = __hmul2(hv2, xv[chunk * 4 + 3]);
            asm volatile("st.shared.v4.b32 [%0], {%1,%2,%3,%4};"
                         :: "r"(ub + i8 * 2),
                            "r"(*reinterpret_cast<uint32_t*>(&p0)),
                            "r"(*reinterpret_cast<uint32_t*>(&p1)),
                            "r"(*reinterpret_cast<uint32_t*>(&p2)),
                            "r"(*reinterpret_cast<uint32_t*>(&p3))
                         : "memory");
        };

        // ---- prologue: stage tile 0 into buf 0 ----
        w_issue(0, 0);
        {
            __half2 hv0 = __half2half2(hsrc[ucol * hstr + uhalf]);
            #pragma unroll
            for (int c = 0; c < 4; ++c) ugen_chunk(hv0, 0, c);
        }
        asm volatile("cp.async.wait_group 0;" ::: "memory");
        __syncthreads();

        // ---- main loop ----
        for (int kt = 0; kt < nk; ++kt) {
            const int cur = kt & 1;
            const int nxt = cur ^ 1;
            const bool more = (kt + 1 < nk);

            __half2 hv2 = __half2half2(__ushort_as_half(0));
            if (more) {
                w_issue(kt + 1, nxt);
                asm volatile("cp.async.wait_group 1;" ::: "memory");
                hv2 = __half2half2(hsrc[ucol * hstr + (2 * (kt + 1) + uhalf)]);
            } else {
                asm volatile("cp.async.wait_group 0;" ::: "memory");
            }

            const uint32_t wcur = sb + OFF_W + (uint32_t)cur * WT_BYTES;
            const uint32_t ucur = sb + OFF_U + (uint32_t)cur * WT_BYTES;

            #pragma unroll
            for (int kk = 0; kk < 4; ++kk) {
                if (more) ugen_chunk(hv2, nxt, kk);

                uint32_t ah[2][4], bh[8][2];
                const uint32_t ka = a_off + kk * 32;
                LDSM4(ah[0], wcur + ka);
                LDSM4(ah[1], wcur + ka + 16 * WSTR_B);
                const uint32_t kb = b_off + kk * 32;
                #pragma unroll
                for (int njp = 0; njp < 4; ++njp) {
                    uint32_t t0[4];
                    LDSM4(t0, ucur + kb + njp * 16 * WSTR_B);
                    bh[2 * njp][0] = t0[0]; bh[2 * njp][1] = t0[1];
                    bh[2 * njp + 1][0] = t0[2]; bh[2 * njp + 1][1] = t0[3];
                }
                #pragma unroll
                for (int mi = 0; mi < 2; ++mi)
                    #pragma unroll
                    for (int nj = 0; nj < 8; ++nj)
                        MMA16816(acc[mi][nj], ah[mi], bh[nj]);
            }
            __syncthreads();   // nxt fully staged AND cur fully consumed
        }

        // ---- epilogue: unscale + bias + ReLU, fp16 hidT store, d-sum ----
        {
            const float* bl = biases[layer];
            #pragma unroll
            for (int mi = 0; mi < 2; ++mi) {
                #pragma unroll
                for (int s = 0; s < 2; ++s) {
                    const int h = o_base + mi * 16 + (lane >> 2) + 8 * s;
                    const float bv = __ldg(&bl[h]);
                    float rs = 0.0f;
                    #pragma unroll
                    for (int nj = 0; nj < 8; ++nj) {
                        float z0 = fmaxf(acc[mi][nj][2 * s] * WINV + bv, 0.0f);
                        float z1 = fmaxf(acc[mi][nj][2 * s + 1] * WINV + bv, 0.0f);
                        rs += z0 + z1;
                        if (layer < 2) {
                            int c0 = col_base + nj * 8 + (lane & 3) * 2;
                            hidT[c0 * HSTR + h] = __float2half_rn(z0);
                            hidT[(c0 + 1) * HSTR + h] = __float2half_rn(z1);
                        }
                    }
                    rs += __shfl_xor_sync(0xFFFFFFFFu, rs, 1);
                    rs += __shfl_xor_sync(0xFFFFFFFFu, rs, 2);
                    if ((lane & 3) == 0)
                        out[(size_t)(b0 + cw) * 384 + layer * 128 + h] = rs;
                }
            }
        }
        __syncthreads();   // hidT complete before next layer's U-gen
    }
}

} // namespace

extern "C" void kernel_launch(void* const* d_in, const int* in_sizes, int n_in,
                              void* d_out, int out_size) {
    const float* x  = (const float*)d_in[0];
    const float* W0 = (const float*)d_in[1];
    const float* b0 = (const float*)d_in[2];
    const float* W1 = (const float*)d_in[3];
    const float* b1 = (const float*)d_in[4];
    const float* W2 = (const float*)d_in[5];
    const float* b2 = (const float*)d_in[6];
    float* out = (float*)d_out;

    prep_w_kernel<<<NTILES, 256>>>(W0, W1, W2);

    cudaFuncSetAttribute(cin_mma_kernel, cudaFuncAttributeMaxDynamicSharedMemorySize,
                         SMEM_TOTAL);
    cin_mma_kernel<<<512, THREADS, SMEM_TOTAL>>>(x, b0, b1, b2, out);
}

// round 14
// speedup vs baseline: 4.3762x; 1.0831x over previous
#include <cuda_runtime.h>
#include <cuda_fp16.h>
#include <cstdint>

// CIN_74603581932155 — single-term fp16 GEMM on warp-level mma.sync (HMMA).
// R13: A (W) operand removed from shared memory. prep pre-bakes W into MMA
// A-fragment layout; main loop LDG.128s fragments from L2 directly into
// registers (distance-2-kk pipeline). Kills A-LDSM + W-STS smem traffic
// (R12 audit: L1 crossbar co-binding with tensor at 2 CTAs/SM).
//
// Per batch-pair CTA:  D(128o x 128col) = W(128 x K) * U^T
//   U[k][col] = hid[h][col] * x0[m][col], k = h*32+m, col = bb*64+d
//   K = 1024 / 4096 / 4096.  fp32 accumulators. W pre-scaled by 2^8 (exact,
//   undone in epilogue) against fp16 subnormals.

namespace {

constexpr int THREADS = 256;
constexpr int NTILE_L0 = 16, NTILE_L12 = 64;
constexpr int NTILES = NTILE_L0 + 2 * NTILE_L12;   // 144
constexpr int WSTR_B = 144;                        // U tile row stride (64 fp16 + pad)
constexpr int WT_BYTES = 128 * WSTR_B;             // 18432 per U tile
constexpr int XSTR = 32;                           // x0T half stride (m < 32)
constexpr int HSTR = 129;                          // hidT half stride (h < 128)
constexpr float WSCALE = 256.0f;
constexpr float WINV   = 1.0f / 256.0f;

constexpr int OFF_U    = 0;                          // [buf] 2 x 18432
constexpr int OFF_X0T  = OFF_U + 2 * WT_BYTES;       // half x0T[128][32]
constexpr int OFF_HIDT = OFF_X0T + 128 * XSTR * 2;   // half hidT[128][129]
constexpr int SMEM_TOTAL = OFF_HIDT + 128 * HSTR * 2;  // 78080
static_assert(SMEM_TOTAL <= 115200, "2-CTA smem budget");

// W in A-fragment layout: per tile 4096 uint32:
//   idx = (((kk*4 + ow)*2 + mi)*32 + lane)*4 + j
//   value = half2{ W[o][k], W[o][k+1] } * 2^8, with
//   o = ow*32 + mi*16 + (lane>>2) + (j&1)*8
//   k = tile_k0 + kk*16 + (lane&3)*2 + (j>>1)*8
__device__ __align__(16) uint32_t g_Wfrag[NTILES * 4096];

__device__ __forceinline__ uint32_t smem_u32(const void* p) {
    uint32_t a;
    asm("{ .reg .u64 t; cvta.to.shared.u64 t, %1; cvt.u32.u64 %0, t; }" : "=r"(a) : "l"(p));
    return a;
}

#define LDGA(r, p) \
    asm volatile("ld.global.nc.v4.u32 {%0,%1,%2,%3}, [%4];" \
        : "=r"((r)[0]), "=r"((r)[1]), "=r"((r)[2]), "=r"((r)[3]) : "l"(p))

#define LDSM4(r, a) \
    asm volatile("ldmatrix.sync.aligned.m8n8.x4.shared.b16 {%0,%1,%2,%3}, [%4];" \
        : "=r"((r)[0]), "=r"((r)[1]), "=r"((r)[2]), "=r"((r)[3]) : "r"(a))

#define MMA16816(d, a, b) \
    asm volatile("mma.sync.aligned.m16n8k16.row.col.f32.f16.f16.f32 " \
        "{%0,%1,%2,%3}, {%4,%5,%6,%7}, {%8,%9}, {%0,%1,%2,%3};" \
        : "+f"((d)[0]), "+f"((d)[1]), "+f"((d)[2]), "+f"((d)[3]) \
        : "r"((a)[0]), "r"((a)[1]), "r"((a)[2]), "r"((a)[3]), "r"((b)[0]), "r"((b)[1]))

// ---------------- prep: W -> fp16 A-fragment layout (pre-scaled by 256) -------
__global__ void prep_w_kernel(const float* __restrict__ W0,
                              const float* __restrict__ W1,
                              const float* __restrict__ W2)
{
    int tile = blockIdx.x;              // 0..143
    int tb; const float* Ws; int K;
    if (tile < NTILE_L0)      { tb = tile;            Ws = W0; K = 1024; }
    else if (tile < 80)       { tb = tile - NTILE_L0; Ws = W1; K = 4096; }
    else                      { tb = tile - 80;       Ws = W2; K = 4096; }

    uint32_t* dst = g_Wfrag + (size_t)tile * 4096;
    for (int i = threadIdx.x; i < 4096; i += blockDim.x) {
        int j    = i & 3;
        int lane = (i >> 2) & 31;
        int mi   = (i >> 7) & 1;
        int ow   = (i >> 8) & 3;
        int kk   = (i >> 10) & 3;
        int o  = ow * 32 + mi * 16 + (lane >> 2) + (j & 1) * 8;
        int kc = kk * 16 + (lane & 3) * 2 + ((j >> 1) & 1) * 8;
        const float* wp = Ws + (size_t)o * K + (size_t)tb * 64 + kc;
        __half2 h = __floats2half2_rn(wp[0] * WSCALE, wp[1] * WSCALE);
        dst[i] = *reinterpret_cast<uint32_t*>(&h);
    }
}

// ---------------- main kernel --------------------------------------------------
__global__ void __launch_bounds__(THREADS, 2)
cin_mma_kernel(const float* __restrict__ x,
               const float* __restrict__ bias0,
               const float* __restrict__ bias1,
               const float* __restrict__ bias2,
               float* __restrict__ out)
{
    extern __shared__ char smem[];
    const uint32_t sb = smem_u32(smem);
    const int tid = threadIdx.x;
    const int wid = tid >> 5;
    const int lane = tid & 31;
    const int b0 = blockIdx.x * 2;

    __half* x0T  = reinterpret_cast<__half*>(smem + OFF_X0T);
    __half* hidT = reinterpret_cast<__half*>(smem + OFF_HIDT);

    // ---- build x0T[col][m] (fp16), col = bb*64 + d ----
    {
        const float* xg = x + (size_t)b0 * 2048;
        #pragma unroll
        for (int r = 0; r < 4; ++r) {
            int idx4 = tid + THREADS * r;           // 0..1023 float4s
            int bb = idx4 >> 9, rem = idx4 & 511;
            int m = rem >> 4, d4 = rem & 15;
            float4 v = *reinterpret_cast<const float4*>(xg + bb * 2048 + m * 64 + d4 * 4);
            int col0 = bb * 64 + d4 * 4;
            x0T[(col0 + 0) * XSTR + m] = __float2half_rn(v.x);
            x0T[(col0 + 1) * XSTR + m] = __float2half_rn(v.y);
            x0T[(col0 + 2) * XSTR + m] = __float2half_rn(v.z);
            x0T[(col0 + 3) * XSTR + m] = __float2half_rn(v.w);
        }
    }
    __syncthreads();

    // ---- per-warp tile mapping: 4(o) x 2(col) warps, warp tile 32 x 64 ----
    const int ow = wid & 3, cw = wid >> 2;
    const int o_base = ow * 32;
    const int col_base = cw * 64;
    const uint32_t b_off = (uint32_t)(col_base + (lane & 7) + ((lane >> 4) << 3)) * WSTR_B
                         + (uint32_t)((lane >> 3) & 1) * 16;

    // per-warp A-fragment base (bytes): + f*4096 + mi*512
    const unsigned char* abase = reinterpret_cast<const unsigned char*>(g_Wfrag)
                               + (size_t)ow * 1024 + (size_t)lane * 16;

    // U-gen role
    const int ucol = tid >> 1;
    const int uhalf = tid & 1;
    const __half2* xv = reinterpret_cast<const __half2*>(x0T + ucol * XSTR);

    const float* biases[3] = {bias0, bias1, bias2};
    const int nk_l[3] = {NTILE_L0, NTILE_L12, NTILE_L12};
    const int tb_l[3] = {0, NTILE_L0, NTILE_L0 + NTILE_L12};

    for (int layer = 0; layer < 3; ++layer) {
        const int nk = nk_l[layer];
        const __half* hsrc = (layer == 0) ? x0T : hidT;
        const int hstr = (layer == 0) ? XSTR : HSTR;

        float acc[2][8][4];
        #pragma unroll
        for (int mi = 0; mi < 2; ++mi)
            #pragma unroll
            for (int nj = 0; nj < 8; ++nj)
                #pragma unroll
                for (int q = 0; q < 4; ++q) acc[mi][nj][q] = 0.0f;

        // ---- U-gen: one 8-value fp16 chunk of tile t into buf ----
        auto ugen_chunk = [&](__half2 hv2, int buf, int chunk) {
            const uint32_t udst = sb + OFF_U + (uint32_t)buf * WT_BYTES;
            const uint32_t ub = udst + (uint32_t)ucol * WSTR_B + (uint32_t)uhalf * 64;
            const int i8 = chunk * 8;
            __half2 p0 = __hmul2(hv2, xv[chunk * 4 + 0]);
            __half2 p1 = __hmul2(hv2, xv[chunk * 4 + 1]);
            __half2 p2 = __hmul2(hv2, xv[chunk * 4 + 2]);
            __half2 p3 = __hmul2(hv2, xv[chunk * 4 + 3]);
            asm volatile("st.shared.v4.b32 [%0], {%1,%2,%3,%4};"
                         :: "r"(ub + i8 * 2),
                            "r"(*reinterpret_cast<uint32_t*>(&p0)),
                            "r"(*reinterpret_cast<uint32_t*>(&p1)),
                            "r"(*reinterpret_cast<uint32_t*>(&p2)),
                            "r"(*reinterpret_cast<uint32_t*>(&p3))
                         : "memory");
        };

        // ---- A-fragment register pipeline (distance 2 kk-steps) ----
        uint32_t areg[2][2][4];            // [slot][mi][4]
        const int fbase = tb_l[layer] * 4;
        const int fend  = fbase + nk * 4;
        LDGA(areg[0][0], abase + (size_t)fbase * 4096);
        LDGA(areg[0][1], abase + (size_t)fbase * 4096 + 512);
        LDGA(areg[1][0], abase + (size_t)(fbase + 1) * 4096);
        LDGA(areg[1][1], abase + (size_t)(fbase + 1) * 4096 + 512);

        // ---- prologue: stage U tile 0 into buf 0 ----
        {
            __half2 hv0 = __half2half2(hsrc[ucol * hstr + uhalf]);
            #pragma unroll
            for (int c = 0; c < 4; ++c) ugen_chunk(hv0, 0, c);
        }
        __syncthreads();

        // ---- main loop ----
        int f = fbase;
        for (int kt = 0; kt < nk; ++kt) {
            const int cur = kt & 1;
            const int nxt = cur ^ 1;
            const bool more = (kt + 1 < nk);

            __half2 hv2 = __half2half2(__ushort_as_half(0));
            if (more)
                hv2 = __half2half2(hsrc[ucol * hstr + (2 * (kt + 1) + uhalf)]);

            const uint32_t ucur = sb + OFF_U + (uint32_t)cur * WT_BYTES;

            #pragma unroll
            for (int kk = 0; kk < 4; ++kk) {
                const int slot = kk & 1;
                if (more) ugen_chunk(hv2, nxt, kk);

                uint32_t bh[8][2];
                const uint32_t kb = b_off + kk * 32;
                #pragma unroll
                for (int njp = 0; njp < 4; ++njp) {
                    uint32_t t0[4];
                    LDSM4(t0, ucur + kb + njp * 16 * WSTR_B);
                    bh[2 * njp][0] = t0[0]; bh[2 * njp][1] = t0[1];
                    bh[2 * njp + 1][0] = t0[2]; bh[2 * njp + 1][1] = t0[3];
                }
                #pragma unroll
                for (int mi = 0; mi < 2; ++mi)
                    #pragma unroll
                    for (int nj = 0; nj < 8; ++nj)
                        MMA16816(acc[mi][nj], areg[slot][mi], bh[nj]);

                // refill this slot with step f+2 (consumed 2 kk from now;
                // issued after the MMAs above -> WAR safe by program order)
                int fn = f + 2; if (fn >= fend) fn = fend - 1;
                LDGA(areg[slot][0], abase + (size_t)fn * 4096);
                LDGA(areg[slot][1], abase + (size_t)fn * 4096 + 512);
                ++f;
            }
            __syncthreads();   // U nxt fully staged AND U cur fully consumed
        }

        // ---- epilogue: unscale + bias + ReLU, fp16 hidT store, d-sum ----
        {
            const float* bl = biases[layer];
            #pragma unroll
            for (int mi = 0; mi < 2; ++mi) {
                #pragma unroll
                for (int s = 0; s < 2; ++s) {
                    const int h = o_base + mi * 16 + (lane >> 2) + 8 * s;
                    const float bv = __ldg(&bl[h]);
                    float rs = 0.0f;
                    #pragma unroll
                    for (int nj = 0; nj < 8; ++nj) {
                        float z0 = fmaxf(acc[mi][nj][2 * s] * WINV + bv, 0.0f);
                        float z1 = fmaxf(acc[mi][nj][2 * s + 1] * WINV + bv, 0.0f);
                        rs += z0 + z1;
                        if (layer < 2) {
                            int c0 = col_base + nj * 8 + (lane & 3) * 2;
                            hidT[c0 * HSTR + h] = __float2half_rn(z0);
                            hidT[(c0 + 1) * HSTR + h] = __float2half_rn(z1);
                        }
                    }
                    rs += __shfl_xor_sync(0xFFFFFFFFu, rs, 1);
                    rs += __shfl_xor_sync(0xFFFFFFFFu, rs, 2);
                    if ((lane & 3) == 0)
                        out[(size_t)(b0 + cw) * 384 + layer * 128 + h] = rs;
                }
            }
        }
        __syncthreads();   // hidT complete before next layer's U-gen
    }
}

} // namespace

extern "C" void kernel_launch(void* const* d_in, const int* in_sizes, int n_in,
                              void* d_out, int out_size) {
    const float* x  = (const float*)d_in[0];
    const float* W0 = (const float*)d_in[1];
    const float* b0 = (const float*)d_in[2];
    const float* W1 = (const float*)d_in[3];
    const float* b1 = (const float*)d_in[4];
    const float* W2 = (const float*)d_in[5];
    const float* b2 = (const float*)d_in[6];
    float* out = (float*)d_out;

    prep_w_kernel<<<NTILES, 256>>>(W0, W1, W2);

    cudaFuncSetAttribute(cin_mma_kernel, cudaFuncAttributeMaxDynamicSharedMemorySize,
                         SMEM_TOTAL);
    cin_mma_kernel<<<512, THREADS, SMEM_TOTAL>>>(x, b0, b1, b2, out);
}

// round 16
// speedup vs baseline: 5.1718x; 1.1818x over previous
#include <cuda_runtime.h>
#include <cuda_fp16.h>
#include <cstdint>

// CIN_74603581932155 — single-term fp16 GEMM on warp-level mma.sync (HMMA).
// R15 = R14 + the missing WAR barrier: a __syncthreads() between each layer's
// k-loop (which READS hidT for B-fragment generation) and its epilogue (which
// OVERWRITES hidT in place). R14 removed all k-loop barriers and with them the
// only separation between those phases -> race -> rel_err 7.7e-3.
//
// Architecture (validated R13/R14 audit):
//  - B fragments computed IN REGISTERS per (nj,kk): LDS.32 hid-pair + x0
//    m-pairs, HMUL2 into MMA half2 packing. No smem U, no B-LDSM, no k-loop
//    barriers (k-loop performs no shared writes).
//  - A (W) pre-baked into MMA A-fragment layout by prep kernel; LDG.128
//    straight from L2 into registers, whole 64-k tile at once.
//
// Per batch-pair CTA:  D(128o x 128col) = W(128 x K) * U^T
//   U[k][col] = hid[h][col] * x0[m][col], k = h*32+m, col = bb*64+d
//   K = 1024 / 4096 / 4096.  fp32 accumulators. W pre-scaled by 2^8 (exact,
//   undone in epilogue) against fp16 subnormals.

namespace {

constexpr int THREADS = 256;
constexpr int NTILE_L0 = 16, NTILE_L12 = 64;
constexpr int NTILES = NTILE_L0 + 2 * NTILE_L12;   // 144
constexpr int XSTR = 40;   // x0T half stride (80B rows)
constexpr int HSTR = 132;  // hidT half stride (264B rows)
constexpr float WSCALE = 256.0f;
constexpr float WINV   = 1.0f / 256.0f;

constexpr int OFF_X0T  = 0;                           // half x0T[128][40]
constexpr int OFF_HIDT = OFF_X0T + 128 * XSTR * 2;    // half hidT[128][132]
constexpr int SMEM_TOTAL = OFF_HIDT + 128 * HSTR * 2; // 44032
static_assert(SMEM_TOTAL <= 115200, "2-CTA smem budget");

// W in A-fragment layout: per tile 4096 uint32:
//   idx = (((kk*4 + ow)*2 + mi)*32 + lane)*4 + j
//   value = half2{ W[o][k], W[o][k+1] } * 2^8, with
//   o = ow*32 + mi*16 + (lane>>2) + (j&1)*8
//   k = tile_k0 + kk*16 + (lane&3)*2 + (j>>1)*8
__device__ __align__(16) uint32_t g_Wfrag[NTILES * 4096];

__device__ __forceinline__ uint32_t smem_u32(const void* p) {
    uint32_t a;
    asm("{ .reg .u64 t; cvta.to.shared.u64 t, %1; cvt.u32.u64 %0, t; }" : "=r"(a) : "l"(p));
    return a;
}

#define LDGA(r, p) \
    asm volatile("ld.global.nc.v4.u32 {%0,%1,%2,%3}, [%4];" \
        : "=r"((r)[0]), "=r"((r)[1]), "=r"((r)[2]), "=r"((r)[3]) : "l"(p))

#define LDS32(r, a) \
    asm volatile("ld.shared.b32 %0, [%1];" : "=r"(r) : "r"(a))

#define MMA16816(d, a, b) \
    asm volatile("mma.sync.aligned.m16n8k16.row.col.f32.f16.f16.f32 " \
        "{%0,%1,%2,%3}, {%4,%5,%6,%7}, {%8,%9}, {%0,%1,%2,%3};" \
        : "+f"((d)[0]), "+f"((d)[1]), "+f"((d)[2]), "+f"((d)[3]) \
        : "r"((a)[0]), "r"((a)[1]), "r"((a)[2]), "r"((a)[3]), "r"((b)[0]), "r"((b)[1]))

// ---------------- prep: W -> fp16 A-fragment layout (pre-scaled by 256) -------
__global__ void prep_w_kernel(const float* __restrict__ W0,
                              const float* __restrict__ W1,
                              const float* __restrict__ W2)
{
    int tile = blockIdx.x;              // 0..143
    int tb; const float* Ws; int K;
    if (tile < NTILE_L0)      { tb = tile;            Ws = W0; K = 1024; }
    else if (tile < 80)       { tb = tile - NTILE_L0; Ws = W1; K = 4096; }
    else                      { tb = tile - 80;       Ws = W2; K = 4096; }

    uint32_t* dst = g_Wfrag + (size_t)tile * 4096;
    for (int i = threadIdx.x; i < 4096; i += blockDim.x) {
        int j    = i & 3;
        int lane = (i >> 2) & 31;
        int mi   = (i >> 7) & 1;
        int ow   = (i >> 8) & 3;
        int kk   = (i >> 10) & 3;
        int o  = ow * 32 + mi * 16 + (lane >> 2) + (j & 1) * 8;
        int kc = kk * 16 + (lane & 3) * 2 + ((j >> 1) & 1) * 8;
        const float* wp = Ws + (size_t)o * K + (size_t)tb * 64 + kc;
        __half2 h = __floats2half2_rn(wp[0] * WSCALE, wp[1] * WSCALE);
        dst[i] = *reinterpret_cast<uint32_t*>(&h);
    }
}

// ---------------- main kernel --------------------------------------------------
__global__ void __launch_bounds__(THREADS, 2)
cin_mma_kernel(const float* __restrict__ x,
               const float* __restrict__ bias0,
               const float* __restrict__ bias1,
               const float* __restrict__ bias2,
               float* __restrict__ out)
{
    extern __shared__ char smem[];
    const uint32_t sb = smem_u32(smem);
    const int tid = threadIdx.x;
    const int wid = tid >> 5;
    const int lane = tid & 31;
    const int b0 = blockIdx.x * 2;

    __half* x0T  = reinterpret_cast<__half*>(smem + OFF_X0T);
    __half* hidT = reinterpret_cast<__half*>(smem + OFF_HIDT);

    // ---- build x0T[col][m] (fp16), col = bb*64 + d ----
    {
        const float* xg = x + (size_t)b0 * 2048;
        #pragma unroll
        for (int r = 0; r < 4; ++r) {
            int idx4 = tid + THREADS * r;           // 0..1023 float4s
            int bb = idx4 >> 9, rem = idx4 & 511;
            int m = rem >> 4, d4 = rem & 15;
            float4 v = *reinterpret_cast<const float4*>(xg + bb * 2048 + m * 64 + d4 * 4);
            int col0 = bb * 64 + d4 * 4;
            x0T[(col0 + 0) * XSTR + m] = __float2half_rn(v.x);
            x0T[(col0 + 1) * XSTR + m] = __float2half_rn(v.y);
            x0T[(col0 + 2) * XSTR + m] = __float2half_rn(v.z);
            x0T[(col0 + 3) * XSTR + m] = __float2half_rn(v.w);
        }
    }
    __syncthreads();

    // ---- per-warp tile mapping: 4(o) x 2(col) warps, warp tile 32 x 64 ----
    const int ow = wid & 3, cw = wid >> 2;
    const int o_base = ow * 32;
    const int col_base = cw * 64;

    // per-thread B-gen column (n = lane>>2 within nj-group)
    const int colq = col_base + (lane >> 2);
    // x0 read base: x0T[colq][ (lane&3)*2 ] (bytes); per nj add nj*8*XSTR*2
    const uint32_t xaddr0 = sb + OFF_X0T
                          + (uint32_t)colq * (XSTR * 2) + (uint32_t)(lane & 3) * 4;

    // per-warp A-fragment base (bytes)
    const unsigned char* abase = reinterpret_cast<const unsigned char*>(g_Wfrag)
                               + (size_t)ow * 1024 + (size_t)lane * 16;

    const float* biases[3] = {bias0, bias1, bias2};
    const int nk_l[3] = {NTILE_L0, NTILE_L12, NTILE_L12};
    const int tb_l[3] = {0, NTILE_L0, NTILE_L0 + NTILE_L12};

    for (int layer = 0; layer < 3; ++layer) {
        const int nk = nk_l[layer];
        // hid source: layer0 reads x0T, else hidT
        const uint32_t hbase = (layer == 0) ? (sb + OFF_X0T) : (sb + OFF_HIDT);
        const int hstrB = ((layer == 0) ? XSTR : HSTR) * 2;
        const uint32_t haddr0 = hbase + (uint32_t)colq * hstrB;

        float acc[2][8][4];
        #pragma unroll
        for (int mi = 0; mi < 2; ++mi)
            #pragma unroll
            for (int nj = 0; nj < 8; ++nj)
                #pragma unroll
                for (int q = 0; q < 4; ++q) acc[mi][nj][q] = 0.0f;

        // A fragments for the whole 64-k tile: [kk][mi][4]
        uint32_t A[4][2][4];
        auto lda_tile = [&](int t) {
            const unsigned char* p = abase + (size_t)(tb_l[layer] + t) * 16384;
            #pragma unroll
            for (int kk = 0; kk < 4; ++kk) {
                LDGA(A[kk][0], p + kk * 4096);
                LDGA(A[kk][1], p + kk * 4096 + 512);
            }
        };
        lda_tile(0);

        // ---- main loop: NO barriers — k-loop does no shared writes ----
        for (int kt = 0; kt < nk; ++kt) {
            const uint32_t hk = haddr0 + (uint32_t)kt * 4;   // half2 {h0,h1}

            #pragma unroll
            for (int nj = 0; nj < 8; ++nj) {
                const uint32_t xo = (uint32_t)nj * (8 * XSTR * 2);
                const uint32_t ho = (uint32_t)nj * (uint32_t)(8 * hstrB);

                uint32_t hraw;
                LDS32(hraw, hk + ho);                        // {hid[h0], hid[h1]}
                __half2 hh = *reinterpret_cast<__half2*>(&hraw);
                __half2 hb[2] = { __half2half2(__low2half(hh)),
                                  __half2half2(__high2half(hh)) };

                uint32_t xr[2][2];                           // [mhalf][klo/khi]
                LDS32(xr[0][0], xaddr0 + xo);                // m pair +0
                LDS32(xr[0][1], xaddr0 + xo + 16);           // m pair +8
                LDS32(xr[1][0], xaddr0 + xo + 32);           // m pair +16
                LDS32(xr[1][1], xaddr0 + xo + 48);           // m pair +24

                #pragma unroll
                for (int hhalf = 0; hhalf < 2; ++hhalf) {
                    #pragma unroll
                    for (int mhalf = 0; mhalf < 2; ++mhalf) {
                        const int kk = hhalf * 2 + mhalf;
                        __half2 u0 = __hmul2(hb[hhalf],
                                             *reinterpret_cast<__half2*>(&xr[mhalf][0]));
                        __half2 u1 = __hmul2(hb[hhalf],
                                             *reinterpret_cast<__half2*>(&xr[mhalf][1]));
                        uint32_t b[2] = { *reinterpret_cast<uint32_t*>(&u0),
                                          *reinterpret_cast<uint32_t*>(&u1) };
                        MMA16816(acc[0][nj], A[kk][0], b);
                        MMA16816(acc[1][nj], A[kk][1], b);
                    }
                }
            }
            // prefetch next tile's A into the same regs (all reads issued above)
            if (kt + 1 < nk) lda_tile(kt + 1);
        }

        // WAR barrier (the R14 bug): all warps must finish READING hidT/x0T
        // for this layer's B fragments before the epilogue OVERWRITES hidT.
        __syncthreads();

        // ---- epilogue: unscale + bias + ReLU, fp16 hidT store, d-sum ----
        {
            const float* bl = biases[layer];
            #pragma unroll
            for (int mi = 0; mi < 2; ++mi) {
                #pragma unroll
                for (int s = 0; s < 2; ++s) {
                    const int h = o_base + mi * 16 + (lane >> 2) + 8 * s;
                    const float bv = __ldg(&bl[h]);
                    float rs = 0.0f;
                    #pragma unroll
                    for (int nj = 0; nj < 8; ++nj) {
                        float z0 = fmaxf(acc[mi][nj][2 * s] * WINV + bv, 0.0f);
                        float z1 = fmaxf(acc[mi][nj][2 * s + 1] * WINV + bv, 0.0f);
                        rs += z0 + z1;
                        if (layer < 2) {
                            int c0 = col_base + nj * 8 + (lane & 3) * 2;
                            hidT[c0 * HSTR + h] = __float2half_rn(z0);
                            hidT[(c0 + 1) * HSTR + h] = __float2half_rn(z1);
                        }
                    }
                    rs += __shfl_xor_sync(0xFFFFFFFFu, rs, 1);
                    rs += __shfl_xor_sync(0xFFFFFFFFu, rs, 2);
                    if ((lane & 3) == 0)
                        out[(size_t)(b0 + cw) * 384 + layer * 128 + h] = rs;
                }
            }
        }
        __syncthreads();   // hidT complete before next layer's B-gen reads
    }
}

} // namespace

extern "C" void kernel_launch(void* const* d_in, const int* in_sizes, int n_in,
                              void* d_out, int out_size) {
    const float* x  = (const float*)d_in[0];
    const float* W0 = (const float*)d_in[1];
    const float* b0 = (const float*)d_in[2];
    const float* W1 = (const float*)d_in[3];
    const float* b1 = (const float*)d_in[4];
    const float* W2 = (const float*)d_in[5];
    const float* b2 = (const float*)d_in[6];
    float* out = (float*)d_out;

    prep_w_kernel<<<NTILES, 256>>>(W0, W1, W2);

    cudaFuncSetAttribute(cin_mma_kernel, cudaFuncAttributeMaxDynamicSharedMemorySize,
                         SMEM_TOTAL);
    cin_mma_kernel<<<512, THREADS, SMEM_TOTAL>>>(x, b0, b1, b2, out);
}